// round 6
// baseline (speedup 1.0000x reference)
#include <cuda_runtime.h>

#define NB    4
#define NP    4096
#define KP    11          // K+1 including self
#define NFEAT 66
#define GC    16          // grid cells per axis
#define NCELL (GC*GC*GC)  // 4096

typedef unsigned long long ull;
#define SENT 0xFFFFFFFFFFFFFFFFull

__device__ float g_Weff[6 * NFEAT];
__device__ float g_beff[6];

// per-batch sorted tables + grid metadata
__device__ float4 g_spos[NB][NP];         // x,y,z,sq  (original bit values)
__device__ int    g_sid [NB][NP];         // sorted -> original index
__device__ int    g_cs  [NB][NCELL + 1];  // cell start offsets
__device__ float  g_meta[NB][8];          // minx,miny,minz, invhx,invhy,invhz, hmin

// ---------------------------------------------------------------------------
// Fold 3 linear layers into one 6x66 affine map.
__global__ void fold_weights_kernel(const float* __restrict__ W1, const float* __restrict__ b1,
                                    const float* __restrict__ W2, const float* __restrict__ b2,
                                    const float* __restrict__ W3, const float* __restrict__ b3) {
    int t = threadIdx.x;
    if (t < NFEAT) {
        float T1[16];
        #pragma unroll
        for (int i = 0; i < 16; ++i) {
            float s = 0.f;
            #pragma unroll
            for (int j = 0; j < 32; ++j) s += W2[i * 32 + j] * W1[j * NFEAT + t];
            T1[i] = s;
        }
        #pragma unroll
        for (int c = 0; c < 6; ++c) {
            float s = 0.f;
            #pragma unroll
            for (int i = 0; i < 16; ++i) s += W3[c * 16 + i] * T1[i];
            g_Weff[c * NFEAT + t] = s;
        }
    } else if (t == NFEAT) {
        float bh[16];
        #pragma unroll
        for (int i = 0; i < 16; ++i) {
            float s = b2[i];
            #pragma unroll
            for (int j = 0; j < 32; ++j) s += W2[i * 32 + j] * b1[j];
            bh[i] = s;
        }
        #pragma unroll
        for (int c = 0; c < 6; ++c) {
            float s = b3[c];
            #pragma unroll
            for (int i = 0; i < 16; ++i) s += W3[c * 16 + i] * bh[i];
            g_beff[c] = s;
        }
    }
}

// ---------------------------------------------------------------------------
// Grid build: one block per batch. bbox -> histogram -> scan -> scatter.
#define BT 512
__global__ void __launch_bounds__(BT)
build_grid_kernel(const float* __restrict__ pos) {
    __shared__ float rmin[3][BT];
    __shared__ float rmax[3][BT];
    __shared__ int   hist[NCELL];     // becomes cell_start, then cursor
    __shared__ int   scan[BT];
    __shared__ float meta[8];

    const int b = blockIdx.x;
    const int t = threadIdx.x;
    const float* pb = pos + (size_t)b * NP * 3;

    // 1) bbox
    float mnx = 3.4e38f, mny = 3.4e38f, mnz = 3.4e38f;
    float mxx = -3.4e38f, mxy = -3.4e38f, mxz = -3.4e38f;
    #pragma unroll
    for (int k = 0; k < NP / BT; ++k) {
        int i = t + k * BT;
        float x = pb[3 * i + 0], y = pb[3 * i + 1], z = pb[3 * i + 2];
        mnx = fminf(mnx, x); mny = fminf(mny, y); mnz = fminf(mnz, z);
        mxx = fmaxf(mxx, x); mxy = fmaxf(mxy, y); mxz = fmaxf(mxz, z);
    }
    rmin[0][t] = mnx; rmin[1][t] = mny; rmin[2][t] = mnz;
    rmax[0][t] = mxx; rmax[1][t] = mxy; rmax[2][t] = mxz;
    __syncthreads();
    for (int s = BT / 2; s > 0; s >>= 1) {
        if (t < s) {
            #pragma unroll
            for (int a = 0; a < 3; ++a) {
                rmin[a][t] = fminf(rmin[a][t], rmin[a][t + s]);
                rmax[a][t] = fmaxf(rmax[a][t], rmax[a][t + s]);
            }
        }
        __syncthreads();
    }
    if (t == 0) {
        #pragma unroll
        for (int a = 0; a < 3; ++a) {
            float lo = rmin[a][0], hi = rmax[a][0];
            float range = hi - lo;
            if (range < 1e-6f) range = 1e-6f;
            range *= 1.0001f;                  // keep points strictly inside
            meta[a]     = lo;
            meta[3 + a] = (float)GC / range;   // inv_h
        }
        float hx = 1.f / meta[3], hy = 1.f / meta[4], hz = 1.f / meta[5];
        meta[6] = fminf(hx, fminf(hy, hz));
        #pragma unroll
        for (int a = 0; a < 8; ++a) g_meta[b][a] = meta[a];
    }
    __syncthreads();

    // 2) histogram
    for (int i = t; i < NCELL; i += BT) hist[i] = 0;
    __syncthreads();
    const float mx0 = meta[0], my0 = meta[1], mz0 = meta[2];
    const float ihx = meta[3], ihy = meta[4], ihz = meta[5];
    #pragma unroll
    for (int k = 0; k < NP / BT; ++k) {
        int i = t + k * BT;
        float x = pb[3 * i + 0], y = pb[3 * i + 1], z = pb[3 * i + 2];
        int cx = min(GC - 1, max(0, (int)((x - mx0) * ihx)));
        int cy = min(GC - 1, max(0, (int)((y - my0) * ihy)));
        int cz = min(GC - 1, max(0, (int)((z - mz0) * ihz)));
        atomicAdd(&hist[(cz * GC + cy) * GC + cx], 1);
    }
    __syncthreads();

    // 3) exclusive scan over NCELL (8 per thread + block scan)
    {
        int vals[NCELL / BT];
        int base = t * (NCELL / BT);
        int s = 0;
        #pragma unroll
        for (int k = 0; k < NCELL / BT; ++k) { vals[k] = hist[base + k]; }
        int ex[NCELL / BT];
        #pragma unroll
        for (int k = 0; k < NCELL / BT; ++k) { ex[k] = s; s += vals[k]; }
        scan[t] = s;
        __syncthreads();
        for (int off = 1; off < BT; off <<= 1) {
            int v = scan[t];
            int add = (t >= off) ? scan[t - off] : 0;
            __syncthreads();
            scan[t] = v + add;
            __syncthreads();
        }
        int blockoff = (t == 0) ? 0 : scan[t - 1];
        #pragma unroll
        for (int k = 0; k < NCELL / BT; ++k) {
            int st = blockoff + ex[k];
            hist[base + k] = st;             // cursor
            g_cs[b][base + k] = st;
        }
        if (t == 0) g_cs[b][NCELL] = NP;
    }
    __syncthreads();

    // 4) scatter (order within a cell is irrelevant: selection keys on (d2,j))
    #pragma unroll
    for (int k = 0; k < NP / BT; ++k) {
        int i = t + k * BT;
        float x = pb[3 * i + 0], y = pb[3 * i + 1], z = pb[3 * i + 2];
        int cx = min(GC - 1, max(0, (int)((x - mx0) * ihx)));
        int cy = min(GC - 1, max(0, (int)((y - my0) * ihy)));
        int cz = min(GC - 1, max(0, (int)((z - mz0) * ihz)));
        int c = (cz * GC + cy) * GC + cx;
        int off = atomicAdd(&hist[c], 1);
        // sq exactly as XLA reduce: ((x*x + y*y) + z*z)
        float sq = __fadd_rn(__fadd_rn(__fmul_rn(x, x), __fmul_rn(y, y)),
                             __fmul_rn(z, z));
        g_spos[b][off] = make_float4(x, y, z, sq);
        g_sid[b][off] = i;
    }
}

// ---------------------------------------------------------------------------
// ordered-uint transform: monotone float -> uint mapping
__device__ __forceinline__ unsigned f2ord(float f) {
    unsigned u = __float_as_uint(f);
    unsigned m = ((int)u >> 31) | 0x80000000u;
    return u ^ m;
}

// Search: one thread per (sorted) query point; exact ring search over grid.
__global__ void __launch_bounds__(64)
search_kernel(const float* __restrict__ pos,
              const float* __restrict__ vel,
              const float* __restrict__ init_cfg,
              float* __restrict__ out) {
    extern __shared__ char smem_raw[];
    float4* sp  = reinterpret_cast<float4*>(smem_raw);            // [NP]
    int*    sid = reinterpret_cast<int*>(sp + NP);                // [NP]
    int*    cs  = sid + NP;                                       // [NCELL+1]
    float*  Wsh = reinterpret_cast<float*>(cs + NCELL + 1);       // [6*NFEAT]
    float*  bsh = Wsh + 6 * NFEAT;                                // [6]

    const int tid = threadIdx.x;
    const int b   = blockIdx.y;
    const int s_q = blockIdx.x * 64 + tid;   // sorted query index

    // stage tables
    for (int i = tid; i < NP; i += 64) { sp[i] = g_spos[b][i]; sid[i] = g_sid[b][i]; }
    for (int i = tid; i < NCELL + 1; i += 64) cs[i] = g_cs[b][i];
    for (int i = tid; i < 6 * NFEAT + 6; i += 64) {
        if (i < 6 * NFEAT) Wsh[i] = g_Weff[i];
        else               bsh[i - 6 * NFEAT] = g_beff[i - 6 * NFEAT];
    }
    __syncthreads();

    const float4 q = sp[s_q];
    const int    n = sid[s_q];               // original index of this query

    const float mx0 = g_meta[b][0], my0 = g_meta[b][1], mz0 = g_meta[b][2];
    const float ihx = g_meta[b][3], ihy = g_meta[b][4], ihz = g_meta[b][5];
    const float hmin = g_meta[b][6];
    const int cx = min(GC - 1, max(0, (int)((q.x - mx0) * ihx)));
    const int cy = min(GC - 1, max(0, (int)((q.y - my0) * ihy)));
    const int cz = min(GC - 1, max(0, (int)((q.z - mz0) * ihz)));

    ull hk[KP];
    #pragma unroll
    for (int s = 0; s < KP; ++s) hk[s] = SENT;

    auto scan_range = [&](int a, int e) {
        for (int i = a; i < e; ++i) {
            float4 p = sp[i];
            float dot = __fmul_rn(q.x, p.x);
            dot = __fmaf_rn(q.y, p.y, dot);
            dot = __fmaf_rn(q.z, p.z, dot);
            float S  = __fadd_rn(q.w, p.w);
            float d2 = __fsub_rn(S, __fmul_rn(2.0f, dot));
            ull key = ((ull)f2ord(d2) << 32) | (unsigned)sid[i];
            if (key < hk[KP - 1]) {
                ull v = key;
                #pragma unroll
                for (int s = 0; s < KP; ++s) {
                    ull a2 = hk[s];
                    ull lo = (v < a2) ? v : a2;
                    v      = (v < a2) ? a2 : v;
                    hk[s] = lo;
                }
            }
        }
    };

    for (int r = 0; r <= GC - 1; ++r) {
        // unprocessed cells (rings >= r) have distance >= (r-1)*hmin
        if (r >= 2 && hk[KP - 1] != SENT) {
            float bd = 0.999f * (float)(r - 1) * hmin;
            unsigned bkey = f2ord(bd * bd);
            if ((unsigned)(hk[KP - 1] >> 32) < bkey) break;
        }
        int zlo = max(cz - r, 0), zhi = min(cz + r, GC - 1);
        for (int z = zlo; z <= zhi; ++z) {
            int adz = abs(z - cz);
            int ylo = max(cy - r, 0), yhi = min(cy + r, GC - 1);
            for (int y = ylo; y <= yhi; ++y) {
                bool face = (adz == r) || (abs(y - cy) == r);
                int rowbase = (z * GC + y) * GC;
                if (face) {
                    int xlo = max(cx - r, 0), xhi = min(cx + r, GC - 1);
                    scan_range(cs[rowbase + xlo], cs[rowbase + xhi + 1]);
                } else {
                    if (cx - r >= 0)      scan_range(cs[rowbase + cx - r], cs[rowbase + cx - r + 1]);
                    if (cx + r <= GC - 1) scan_range(cs[rowbase + cx + r], cs[rowbase + cx + r + 1]);
                }
            }
        }
    }

    // ---- epilogue: feats @ Weff^T + beff, fused gather ----
    float acc[6];
    #pragma unroll
    for (int c = 0; c < 6; ++c) acc[c] = bsh[c];

    const float* posb = pos + (size_t)b * NP * 3;
    const float* velb = vel + (size_t)b * NP * 3;
    #pragma unroll
    for (int kk = 0; kk < KP; ++kk) {
        const int idx = (int)(hk[kk] & 0xFFFFFFFFull);
        float vx = velb[3 * idx + 0];
        float vy = velb[3 * idx + 1];
        float vz = velb[3 * idx + 2];
        const int fv = 30 + kk * 3;
        #pragma unroll
        for (int c = 0; c < 6; ++c)
            acc[c] += Wsh[c * NFEAT + fv + 0] * vx
                    + Wsh[c * NFEAT + fv + 1] * vy
                    + Wsh[c * NFEAT + fv + 2] * vz;
        if (kk >= 1) {
            float ox = posb[3 * idx + 0] - q.x;
            float oy = posb[3 * idx + 1] - q.y;
            float oz = posb[3 * idx + 2] - q.z;
            const int fo = (kk - 1) * 3;
            #pragma unroll
            for (int c = 0; c < 6; ++c)
                acc[c] += Wsh[c * NFEAT + fo + 0] * ox
                        + Wsh[c * NFEAT + fo + 1] * oy
                        + Wsh[c * NFEAT + fo + 2] * oz;
        }
    }
    float i0 = init_cfg[b * 3 + 0];
    float i1 = init_cfg[b * 3 + 1];
    float i2 = init_cfg[b * 3 + 2];
    #pragma unroll
    for (int c = 0; c < 6; ++c)
        acc[c] += Wsh[c * NFEAT + 63] * i0
                + Wsh[c * NFEAT + 64] * i1
                + Wsh[c * NFEAT + 65] * i2;

    acc[0] += q.x; acc[1] += q.y; acc[2] += q.z;

    float* o = out + ((size_t)b * NP + n) * 6;
    #pragma unroll
    for (int c = 0; c < 6; ++c) o[c] = acc[c];
}

extern "C" void kernel_launch(void* const* d_in, const int* in_sizes, int n_in,
                              void* d_out, int out_size) {
    const float* pos      = (const float*)d_in[0];
    const float* vel      = (const float*)d_in[1];
    const float* init_cfg = (const float*)d_in[2];
    const float* W1 = (const float*)d_in[3];
    const float* b1 = (const float*)d_in[4];
    const float* W2 = (const float*)d_in[5];
    const float* b2 = (const float*)d_in[6];
    const float* W3 = (const float*)d_in[7];
    const float* b3 = (const float*)d_in[8];
    float* out = (float*)d_out;

    fold_weights_kernel<<<1, 96>>>(W1, b1, W2, b2, W3, b3);
    build_grid_kernel<<<NB, BT>>>(pos);

    size_t shmem = (size_t)NP * sizeof(float4)     // sp
                 + (size_t)NP * sizeof(int)        // sid
                 + (NCELL + 1) * sizeof(int)       // cs
                 + (6 * NFEAT + 6) * sizeof(float);
    cudaFuncSetAttribute(search_kernel,
                         cudaFuncAttributeMaxDynamicSharedMemorySize, (int)shmem);
    dim3 grid(NP / 64, NB);
    search_kernel<<<grid, 64, shmem>>>(pos, vel, init_cfg, out);
}

// round 8
// speedup vs baseline: 1.8464x; 1.8464x over previous
#include <cuda_runtime.h>

#define NB    4
#define NP    4096
#define KP    11          // K+1 including self
#define NFEAT 66
#define GC    16          // grid cells per axis
#define NCELL (GC*GC*GC)  // 4096
#define QPB   64          // queries per block (search)
#define LPQ   4           // lanes per query

typedef unsigned long long ull;
#define SENT 0xFFFFFFFFFFFFFFFFull

__device__ float g_Weff[6 * NFEAT];
__device__ float g_beff[6];

// per-batch sorted tables + grid metadata
__device__ float4 g_spos[NB][NP];         // x,y,z,sq (original bit values)
__device__ int    g_sid [NB][NP];         // sorted -> original index
__device__ int    g_cs  [NB][NCELL + 1];  // cell start offsets
__device__ float  g_meta[NB][8];          // minx,miny,minz, invhx,invhy,invhz, hmin

// ---------------------------------------------------------------------------
// Fold 3 linear layers into one 6x66 affine map (parallel, 2 phases).
__global__ void __launch_bounds__(416)
fold_weights_kernel(const float* __restrict__ W1, const float* __restrict__ b1,
                    const float* __restrict__ W2, const float* __restrict__ b2,
                    const float* __restrict__ W3, const float* __restrict__ b3) {
    __shared__ float W32[6 * 32];   // W3 @ W2
    __shared__ float bh[16];        // W2 @ b1 + b2
    int t = threadIdx.x;
    if (t < 192) {                  // c = t/32, jj = t%32
        int c = t >> 5, jj = t & 31;
        float s = 0.f;
        #pragma unroll
        for (int i = 0; i < 16; ++i) s += W3[c * 16 + i] * W2[i * 32 + jj];
        W32[c * 32 + jj] = s;
    } else if (t < 208) {           // i = t-192
        int i = t - 192;
        float s = b2[i];
        #pragma unroll
        for (int j = 0; j < 32; ++j) s += W2[i * 32 + j] * b1[j];
        bh[i] = s;
    }
    __syncthreads();
    if (t < 396) {                  // c = t/66, f = t%66
        int c = t / NFEAT, f = t % NFEAT;
        float s = 0.f;
        #pragma unroll
        for (int jj = 0; jj < 32; ++jj) s += W32[c * 32 + jj] * W1[jj * NFEAT + f];
        g_Weff[c * NFEAT + f] = s;
    } else if (t < 402) {
        int c = t - 396;
        float s = b3[c];
        #pragma unroll
        for (int i = 0; i < 16; ++i) s += W3[c * 16 + i] * bh[i];
        g_beff[c] = s;
    }
}

// ---------------------------------------------------------------------------
// Grid build: one block per batch. bbox -> histogram -> scan -> scatter.
#define BT 512
__global__ void __launch_bounds__(BT)
build_grid_kernel(const float* __restrict__ pos) {
    __shared__ float rmin[3][BT];
    __shared__ float rmax[3][BT];
    __shared__ int   hist[NCELL];     // becomes cursor
    __shared__ int   scan[BT];
    __shared__ float meta[8];

    const int b = blockIdx.x;
    const int t = threadIdx.x;
    const float* pb = pos + (size_t)b * NP * 3;

    // 1) bbox
    float mnx = 3.4e38f, mny = 3.4e38f, mnz = 3.4e38f;
    float mxx = -3.4e38f, mxy = -3.4e38f, mxz = -3.4e38f;
    #pragma unroll
    for (int k = 0; k < NP / BT; ++k) {
        int i = t + k * BT;
        float x = pb[3 * i + 0], y = pb[3 * i + 1], z = pb[3 * i + 2];
        mnx = fminf(mnx, x); mny = fminf(mny, y); mnz = fminf(mnz, z);
        mxx = fmaxf(mxx, x); mxy = fmaxf(mxy, y); mxz = fmaxf(mxz, z);
    }
    rmin[0][t] = mnx; rmin[1][t] = mny; rmin[2][t] = mnz;
    rmax[0][t] = mxx; rmax[1][t] = mxy; rmax[2][t] = mxz;
    __syncthreads();
    for (int s = BT / 2; s > 0; s >>= 1) {
        if (t < s) {
            #pragma unroll
            for (int a = 0; a < 3; ++a) {
                rmin[a][t] = fminf(rmin[a][t], rmin[a][t + s]);
                rmax[a][t] = fmaxf(rmax[a][t], rmax[a][t + s]);
            }
        }
        __syncthreads();
    }
    if (t == 0) {
        #pragma unroll
        for (int a = 0; a < 3; ++a) {
            float lo = rmin[a][0], hi = rmax[a][0];
            float range = hi - lo;
            if (range < 1e-6f) range = 1e-6f;
            range *= 1.0001f;
            meta[a]     = lo;
            meta[3 + a] = (float)GC / range;
        }
        float hx = 1.f / meta[3], hy = 1.f / meta[4], hz = 1.f / meta[5];
        meta[6] = fminf(hx, fminf(hy, hz));
        #pragma unroll
        for (int a = 0; a < 8; ++a) g_meta[b][a] = meta[a];
    }
    __syncthreads();

    // 2) histogram
    for (int i = t; i < NCELL; i += BT) hist[i] = 0;
    __syncthreads();
    const float mx0 = meta[0], my0 = meta[1], mz0 = meta[2];
    const float ihx = meta[3], ihy = meta[4], ihz = meta[5];
    #pragma unroll
    for (int k = 0; k < NP / BT; ++k) {
        int i = t + k * BT;
        float x = pb[3 * i + 0], y = pb[3 * i + 1], z = pb[3 * i + 2];
        int cx = min(GC - 1, max(0, (int)((x - mx0) * ihx)));
        int cy = min(GC - 1, max(0, (int)((y - my0) * ihy)));
        int cz = min(GC - 1, max(0, (int)((z - mz0) * ihz)));
        atomicAdd(&hist[(cz * GC + cy) * GC + cx], 1);
    }
    __syncthreads();

    // 3) exclusive scan over NCELL
    {
        int base = t * (NCELL / BT);
        int s = 0;
        int ex[NCELL / BT];
        #pragma unroll
        for (int k = 0; k < NCELL / BT; ++k) { ex[k] = s; s += hist[base + k]; }
        scan[t] = s;
        __syncthreads();
        for (int off = 1; off < BT; off <<= 1) {
            int v = scan[t];
            int add = (t >= off) ? scan[t - off] : 0;
            __syncthreads();
            scan[t] = v + add;
            __syncthreads();
        }
        int blockoff = (t == 0) ? 0 : scan[t - 1];
        #pragma unroll
        for (int k = 0; k < NCELL / BT; ++k) {
            int st = blockoff + ex[k];
            hist[base + k] = st;
            g_cs[b][base + k] = st;
        }
        if (t == 0) g_cs[b][NCELL] = NP;
    }
    __syncthreads();

    // 4) scatter
    #pragma unroll
    for (int k = 0; k < NP / BT; ++k) {
        int i = t + k * BT;
        float x = pb[3 * i + 0], y = pb[3 * i + 1], z = pb[3 * i + 2];
        int cx = min(GC - 1, max(0, (int)((x - mx0) * ihx)));
        int cy = min(GC - 1, max(0, (int)((y - my0) * ihy)));
        int cz = min(GC - 1, max(0, (int)((z - mz0) * ihz)));
        int c = (cz * GC + cy) * GC + cx;
        int off = atomicAdd(&hist[c], 1);
        float sq = __fadd_rn(__fadd_rn(__fmul_rn(x, x), __fmul_rn(y, y)),
                             __fmul_rn(z, z));
        g_spos[b][off] = make_float4(x, y, z, sq);
        g_sid[b][off] = i;
    }
}

// ---------------------------------------------------------------------------
__device__ __forceinline__ unsigned f2ord(float f) {
    unsigned u = __float_as_uint(f);
    unsigned m = ((int)u >> 31) | 0x80000000u;
    return u ^ m;
}

// Search: 4 lanes per query, ring search over grid, per-lane top-11 (u64 keys),
// quad merge. Distance arithmetic bit-pinned to the reference lowering.
// NOTE: the ring-break quad reduction uses the QUAD's member mask only —
// quads of the same warp exit the ring loop at different r, so a full-warp
// mask shuffle there deadlocks (R7 bug).
__global__ void __launch_bounds__(QPB * LPQ)
search_kernel(const float* __restrict__ pos,
              const float* __restrict__ vel,
              const float* __restrict__ init_cfg,
              float* __restrict__ out) {
    extern __shared__ char smem_raw[];
    float4* sp   = reinterpret_cast<float4*>(smem_raw);           // [NP] 64KB
    int*    sid  = reinterpret_cast<int*>(sp + NP);               // [NP] 16KB
    float*  Wsh  = reinterpret_cast<float*>(sid + NP);            // 396
    float*  bsh  = Wsh + 6 * NFEAT;                               // 6 (+pad)
    ull*    mbuf = reinterpret_cast<ull*>(bsh + 6 + 4);           // QPB*LPQ*KP

    const int tid    = threadIdx.x;
    const int qlocal = tid / LPQ;
    const int lane   = tid % LPQ;
    const int b      = blockIdx.y;
    const int s_q    = blockIdx.x * QPB + qlocal;   // sorted query index
    // member mask of this thread's quad within its warp
    const unsigned qmask = 0xFu << (((unsigned)tid & 31u) & ~3u);

    for (int i = tid; i < NP; i += QPB * LPQ) { sp[i] = g_spos[b][i]; sid[i] = g_sid[b][i]; }
    for (int i = tid; i < 6 * NFEAT + 6; i += QPB * LPQ) {
        if (i < 6 * NFEAT) Wsh[i] = g_Weff[i];
        else               bsh[i - 6 * NFEAT] = g_beff[i - 6 * NFEAT];
    }
    __syncthreads();

    const float4 q = sp[s_q];
    const int    n = sid[s_q];                      // original query index

    const float mx0 = g_meta[b][0], my0 = g_meta[b][1], mz0 = g_meta[b][2];
    const float ihx = g_meta[b][3], ihy = g_meta[b][4], ihz = g_meta[b][5];
    const float hmin = g_meta[b][6];
    const int cx = min(GC - 1, max(0, (int)((q.x - mx0) * ihx)));
    const int cy = min(GC - 1, max(0, (int)((q.y - my0) * ihy)));
    const int cz = min(GC - 1, max(0, (int)((q.z - mz0) * ihz)));

    ull hk[KP];
    #pragma unroll
    for (int s = 0; s < KP; ++s) hk[s] = SENT;

    const int* csb = g_cs[b];

    auto scan_range = [&](int a, int e) {
        for (int i = a + lane; i < e; i += LPQ) {
            float4 p = sp[i];
            float dot = __fmul_rn(q.x, p.x);
            dot = __fmaf_rn(q.y, p.y, dot);
            dot = __fmaf_rn(q.z, p.z, dot);
            float S  = __fadd_rn(q.w, p.w);
            float d2 = __fsub_rn(S, __fmul_rn(2.0f, dot));
            ull key = ((ull)f2ord(d2) << 32) | (unsigned)sid[i];
            if (key < hk[KP - 1]) {
                hk[KP - 1] = key;
                #pragma unroll
                for (int s = KP - 1; s > 0; --s) {
                    if (hk[s] < hk[s - 1]) { ull tsw = hk[s - 1]; hk[s - 1] = hk[s]; hk[s] = tsw; }
                    else break;
                }
            }
        }
    };

    for (int r = 0; r <= GC - 1; ++r) {
        if (r >= 2) {
            // merged 11th <= quad-min of lane-11ths (conservative, exact).
            // Quad lanes are control-flow convergent here; use quad mask only.
            unsigned h = (unsigned)(hk[KP - 1] >> 32);
            h = min(h, __shfl_xor_sync(qmask, h, 1));
            h = min(h, __shfl_xor_sync(qmask, h, 2));
            float bd = 0.999f * (float)(r - 1) * hmin;
            if (h < f2ord(bd * bd)) break;
        }
        int zlo = max(cz - r, 0), zhi = min(cz + r, GC - 1);
        for (int z = zlo; z <= zhi; ++z) {
            int adz = abs(z - cz);
            int ylo = max(cy - r, 0), yhi = min(cy + r, GC - 1);
            for (int y = ylo; y <= yhi; ++y) {
                bool face = (adz == r) || (abs(y - cy) == r);
                int rowbase = (z * GC + y) * GC;
                if (face) {
                    int xlo = max(cx - r, 0), xhi = min(cx + r, GC - 1);
                    scan_range(__ldg(&csb[rowbase + xlo]), __ldg(&csb[rowbase + xhi + 1]));
                } else {
                    if (cx - r >= 0)
                        scan_range(__ldg(&csb[rowbase + cx - r]), __ldg(&csb[rowbase + cx - r + 1]));
                    if (cx + r <= GC - 1)
                        scan_range(__ldg(&csb[rowbase + cx + r]), __ldg(&csb[rowbase + cx + r + 1]));
                }
            }
        }
    }

    // publish per-lane sorted lists
    {
        const int base = tid * KP;
        #pragma unroll
        for (int s = 0; s < KP; ++s) mbuf[base + s] = hk[s];
    }
    __syncwarp();

    if (lane == 0) {
        // stable 4-way merge on u64 keys (d2 asc, then orig idx asc)
        int sel[KP];
        int p0 = 0, p1 = 0, p2 = 0, p3 = 0;
        const int base = qlocal * LPQ * KP;
        #pragma unroll
        for (int s = 0; s < KP; ++s) {
            ull k0 = mbuf[base + 0 * KP + p0];
            ull k1 = mbuf[base + 1 * KP + p1];
            ull k2 = mbuf[base + 2 * KP + p2];
            ull k3 = mbuf[base + 3 * KP + p3];
            ull bk = k0; int bl = 0;
            if (k1 < bk) { bk = k1; bl = 1; }
            if (k2 < bk) { bk = k2; bl = 2; }
            if (k3 < bk) { bk = k3; bl = 3; }
            sel[s] = (int)(bk & 0xFFFFFFFFull);
            if      (bl == 0) ++p0;
            else if (bl == 1) ++p1;
            else if (bl == 2) ++p2;
            else              ++p3;
        }

        // ---- epilogue: feats @ Weff^T + beff, fused gather ----
        float acc[6];
        #pragma unroll
        for (int c = 0; c < 6; ++c) acc[c] = bsh[c];

        const float* posb = pos + (size_t)b * NP * 3;
        const float* velb = vel + (size_t)b * NP * 3;
        #pragma unroll
        for (int kk = 0; kk < KP; ++kk) {
            const int idx = sel[kk];
            float vx = velb[3 * idx + 0];
            float vy = velb[3 * idx + 1];
            float vz = velb[3 * idx + 2];
            const int fv = 30 + kk * 3;
            #pragma unroll
            for (int c = 0; c < 6; ++c)
                acc[c] += Wsh[c * NFEAT + fv + 0] * vx
                        + Wsh[c * NFEAT + fv + 1] * vy
                        + Wsh[c * NFEAT + fv + 2] * vz;
            if (kk >= 1) {
                float ox = posb[3 * idx + 0] - q.x;
                float oy = posb[3 * idx + 1] - q.y;
                float oz = posb[3 * idx + 2] - q.z;
                const int fo = (kk - 1) * 3;
                #pragma unroll
                for (int c = 0; c < 6; ++c)
                    acc[c] += Wsh[c * NFEAT + fo + 0] * ox
                            + Wsh[c * NFEAT + fo + 1] * oy
                            + Wsh[c * NFEAT + fo + 2] * oz;
            }
        }
        float i0 = init_cfg[b * 3 + 0];
        float i1 = init_cfg[b * 3 + 1];
        float i2 = init_cfg[b * 3 + 2];
        #pragma unroll
        for (int c = 0; c < 6; ++c)
            acc[c] += Wsh[c * NFEAT + 63] * i0
                    + Wsh[c * NFEAT + 64] * i1
                    + Wsh[c * NFEAT + 65] * i2;

        acc[0] += q.x; acc[1] += q.y; acc[2] += q.z;

        float* o = out + ((size_t)b * NP + n) * 6;
        #pragma unroll
        for (int c = 0; c < 6; ++c) o[c] = acc[c];
    }
}

extern "C" void kernel_launch(void* const* d_in, const int* in_sizes, int n_in,
                              void* d_out, int out_size) {
    const float* pos      = (const float*)d_in[0];
    const float* vel      = (const float*)d_in[1];
    const float* init_cfg = (const float*)d_in[2];
    const float* W1 = (const float*)d_in[3];
    const float* b1 = (const float*)d_in[4];
    const float* W2 = (const float*)d_in[5];
    const float* b2 = (const float*)d_in[6];
    const float* W3 = (const float*)d_in[7];
    const float* b3 = (const float*)d_in[8];
    float* out = (float*)d_out;

    fold_weights_kernel<<<1, 416>>>(W1, b1, W2, b2, W3, b3);
    build_grid_kernel<<<NB, BT>>>(pos);

    size_t shmem = (size_t)NP * sizeof(float4)            // sp
                 + (size_t)NP * sizeof(int)               // sid
                 + (6 * NFEAT + 6 + 4) * sizeof(float)    // W, b, pad
                 + (size_t)QPB * LPQ * KP * sizeof(ull);  // merge buffers
    cudaFuncSetAttribute(search_kernel,
                         cudaFuncAttributeMaxDynamicSharedMemorySize, (int)shmem);
    dim3 grid(NP / QPB, NB);
    search_kernel<<<grid, QPB * LPQ, shmem>>>(pos, vel, init_cfg, out);
}

// round 10
// speedup vs baseline: 2.0190x; 1.0935x over previous
#include <cuda_runtime.h>

#define NB    4
#define NP    4096
#define KP    11                 // K+1 including self
#define NFEAT 66
#define GC    16                 // grid cells per axis
#define NCELL (GC*GC*GC)         // 4096
#define XMIN  (-4.5f)
#define HCELL (9.0f/(float)GC)   // 0.5625
#define IHINV ((float)GC/9.0f)
#define WPQ   8                  // warps (queries) per search block

typedef unsigned long long ull;
#define SENT 0xFFFFFFFFFFFFFFFFull

__device__ float  g_Weff[6 * NFEAT];
__device__ float  g_beff[6];
__device__ float4 g_spos[NB][NP];          // x,y,z, idx-as-float-bits
__device__ int    g_cs[NB][NCELL + 1];
__device__ int    g_hist[NB][NCELL];
__device__ int    g_cursor[NB][NCELL];

__device__ __forceinline__ int cell1(float v) {
    int c = (int)(__fmul_rn(__fsub_rn(v, XMIN), IHINV));
    return min(GC - 1, max(0, c));
}
__device__ __forceinline__ unsigned f2ord(float f) {
    unsigned u = __float_as_uint(f);
    return u ^ (((int)u >> 31) | 0x80000000u);
}

// ---------------------------------------------------------------------------
__global__ void zero_kernel() {
    reinterpret_cast<int*>(g_hist)[blockIdx.x * 1024 + threadIdx.x] = 0;
}

// ---------------------------------------------------------------------------
// Fold 3 linear layers into one 6x66 affine map; weights staged via smem.
__global__ void __launch_bounds__(512)
fold_weights_kernel(const float* __restrict__ W1, const float* __restrict__ b1,
                    const float* __restrict__ W2, const float* __restrict__ b2,
                    const float* __restrict__ W3, const float* __restrict__ b3) {
    __shared__ float sW1[32 * NFEAT];
    __shared__ float sW2[16 * 32];
    __shared__ float sW3[6 * 16];
    __shared__ float sb1[32], sb2[16];
    __shared__ float W32[6 * 32];
    __shared__ float bh[16];
    int t = threadIdx.x;
    for (int i = t; i < 32 * NFEAT; i += 512) sW1[i] = W1[i];
    for (int i = t; i < 512; i += 512)        sW2[i] = W2[i];
    if (t < 96) sW3[t] = W3[t];
    if (t < 32) sb1[t] = b1[t];
    if (t < 16) sb2[t] = b2[t];
    __syncthreads();
    if (t < 192) {                      // W32 = W3 @ W2
        int c = t >> 5, jj = t & 31;
        float s = 0.f;
        #pragma unroll
        for (int i = 0; i < 16; ++i) s += sW3[c * 16 + i] * sW2[i * 32 + jj];
        W32[c * 32 + jj] = s;
    } else if (t < 208) {               // bh = W2 @ b1 + b2
        int i = t - 192;
        float s = sb2[i];
        #pragma unroll
        for (int j = 0; j < 32; ++j) s += sW2[i * 32 + j] * sb1[j];
        bh[i] = s;
    }
    __syncthreads();
    if (t < 396) {                      // Weff = W32 @ W1
        int c = t / NFEAT, f = t % NFEAT;
        float s = 0.f;
        #pragma unroll
        for (int jj = 0; jj < 32; ++jj) s += W32[c * 32 + jj] * sW1[jj * NFEAT + f];
        g_Weff[c * NFEAT + f] = s;
    } else if (t < 402) {               // beff = W3 @ bh + b3
        int c = t - 396;
        float s = b3[c];
        #pragma unroll
        for (int i = 0; i < 16; ++i) s += sW3[c * 16 + i] * bh[i];
        g_beff[c] = s;
    }
}

// ---------------------------------------------------------------------------
__global__ void hist_kernel(const float* __restrict__ pos) {
    int idx = blockIdx.x * 256 + threadIdx.x;     // 64 blocks x 256 = NB*NP
    int b = idx >> 12, i = idx & (NP - 1);
    const float* p = pos + ((size_t)b * NP + i) * 3;
    float x = p[0], y = p[1], z = p[2];
    int c = (cell1(z) * GC + cell1(y)) * GC + cell1(x);
    atomicAdd(&g_hist[b][c], 1);
}

__global__ void __launch_bounds__(512) scan_kernel() {
    __shared__ int sc[512];
    int b = blockIdx.x, t = threadIdx.x;
    int base = t * 8;
    int ex[8]; int s = 0;
    #pragma unroll
    for (int k = 0; k < 8; ++k) { ex[k] = s; s += g_hist[b][base + k]; }
    sc[t] = s; __syncthreads();
    for (int off = 1; off < 512; off <<= 1) {
        int v = sc[t];
        int add = (t >= off) ? sc[t - off] : 0;
        __syncthreads();
        sc[t] = v + add;
        __syncthreads();
    }
    int bo = t ? sc[t - 1] : 0;
    #pragma unroll
    for (int k = 0; k < 8; ++k) {
        int st = bo + ex[k];
        g_cs[b][base + k] = st;
        g_cursor[b][base + k] = st;
    }
    if (t == 0) g_cs[b][NCELL] = NP;
}

__global__ void scatter_kernel(const float* __restrict__ pos) {
    int idx = blockIdx.x * 256 + threadIdx.x;
    int b = idx >> 12, i = idx & (NP - 1);
    const float* p = pos + ((size_t)b * NP + i) * 3;
    float x = p[0], y = p[1], z = p[2];
    int c = (cell1(z) * GC + cell1(y)) * GC + cell1(x);
    int off = atomicAdd(&g_cursor[b][c], 1);
    g_spos[b][off] = make_float4(x, y, z, __int_as_float(i));
}

// ---------------------------------------------------------------------------
// Search: ONE WARP PER QUERY (fully convergent ring walk). Per-lane top-11
// on u64 keys (ord(d2)<<32 | orig_idx), warp merge via 11-round min-extract.
// d2 arithmetic bit-pinned to the reference's XLA lowering.
__global__ void __launch_bounds__(WPQ * 32, 2)
search_kernel(const float* __restrict__ pos,
              const float* __restrict__ vel,
              const float* __restrict__ init_cfg,
              float* __restrict__ out) {
    __shared__ float Wsh[6 * NFEAT];
    __shared__ float bsh[8];
    const int tid = threadIdx.x;
    for (int i = tid; i < 6 * NFEAT; i += WPQ * 32) Wsh[i] = g_Weff[i];
    if (tid < 6) bsh[tid] = g_beff[tid];
    __syncthreads();

    const int wid  = tid >> 5;
    const int lane = tid & 31;
    const int b    = blockIdx.y;
    const int s_q  = blockIdx.x * WPQ + wid;      // sorted query index

    const float4 q = g_spos[b][s_q];
    const int    n = __float_as_int(q.w);         // original query index
    const float qsq = __fadd_rn(__fadd_rn(__fmul_rn(q.x, q.x), __fmul_rn(q.y, q.y)),
                                __fmul_rn(q.z, q.z));
    const int cx = cell1(q.x), cy = cell1(q.y), cz = cell1(q.z);
    const int*    csb = g_cs[b];
    const float4* sp  = g_spos[b];

    ull hk[KP];
    #pragma unroll
    for (int s = 0; s < KP; ++s) hk[s] = SENT;

    auto scan_range = [&](int a, int e) {
        for (int i = a + lane; i < e; i += 32) {
            float4 p = __ldg(&sp[i]);
            float psq = __fadd_rn(__fadd_rn(__fmul_rn(p.x, p.x), __fmul_rn(p.y, p.y)),
                                  __fmul_rn(p.z, p.z));
            float dot = __fmul_rn(q.x, p.x);
            dot = __fmaf_rn(q.y, p.y, dot);
            dot = __fmaf_rn(q.z, p.z, dot);
            float S  = __fadd_rn(qsq, psq);
            float d2 = __fsub_rn(S, __fmul_rn(2.0f, dot));
            ull key = ((ull)f2ord(d2) << 32) | (unsigned)__float_as_int(p.w);
            if (key < hk[KP - 1]) {
                hk[KP - 1] = key;
                #pragma unroll
                for (int s = KP - 1; s > 0; --s) {
                    if (hk[s] < hk[s - 1]) { ull t2 = hk[s - 1]; hk[s - 1] = hk[s]; hk[s] = t2; }
                    else break;
                }
            }
        }
    };

    int myn = 0;   // lane s (s<11) ends up holding neighbor s's original index

    // warp-cooperative exact merge: 11 rounds of min-extraction over lane lists.
    // Non-destructive on hk. Returns the merged 11th-smallest key.
    auto merge11 = [&]() -> ull {
        ull ck[KP];
        #pragma unroll
        for (int s = 0; s < KP; ++s) ck[s] = hk[s];
        ull m_last = SENT;
        #pragma unroll
        for (int s = 0; s < KP; ++s) {
            ull m = ck[0];
            #pragma unroll
            for (int o = 16; o > 0; o >>= 1) {
                ull t2 = __shfl_xor_sync(0xFFFFFFFFu, m, o);
                if (t2 < m) m = t2;
            }
            if (lane == s) myn = (int)(m & 0xFFFFFFFFull);
            if (ck[0] == m) {                      // unique key -> exactly one lane pops
                #pragma unroll
                for (int t2 = 0; t2 < KP - 1; ++t2) ck[t2] = ck[t2 + 1];
                ck[KP - 1] = SENT;
            }
            m_last = m;
        }
        return m_last;
    };

    // rings 0..1: 3x3x3 neighborhood (skip out-of-range, never duplicate)
    #pragma unroll
    for (int dz = -1; dz <= 1; ++dz) {
        int z = cz + dz; if ((unsigned)z >= GC) continue;
        #pragma unroll
        for (int dy = -1; dy <= 1; ++dy) {
            int y = cy + dy; if ((unsigned)y >= GC) continue;
            int rb = (z * GC + y) * GC;
            int xlo = max(cx - 1, 0), xhi = min(cx + 1, GC - 1);
            scan_range(__ldg(&csb[rb + xlo]), __ldg(&csb[rb + xhi + 1]));
        }
    }

    bool done = false;
    for (int r = 2; r <= GC - 1 && !done; ++r) {
        // unscanned cells are rings >= r: all points >= (r-1)*H away (clamping
        // to the box is a contraction, so this holds for true coordinates too)
        ull m11 = merge11();
        float bd = 0.999f * (float)(r - 1) * HCELL;
        if ((unsigned)(m11 >> 32) < f2ord(__fmul_rn(bd, bd))) { done = true; break; }
        int zlo = max(cz - r, 0), zhi = min(cz + r, GC - 1);
        for (int z = zlo; z <= zhi; ++z) {
            int adz = abs(z - cz);
            int ylo = max(cy - r, 0), yhi = min(cy + r, GC - 1);
            for (int y = ylo; y <= yhi; ++y) {
                bool face = (adz == r) || (abs(y - cy) == r);
                int rb = (z * GC + y) * GC;
                if (face) {
                    int xlo = max(cx - r, 0), xhi = min(cx + r, GC - 1);
                    scan_range(__ldg(&csb[rb + xlo]), __ldg(&csb[rb + xhi + 1]));
                } else {
                    if (cx - r >= 0)
                        scan_range(__ldg(&csb[rb + cx - r]), __ldg(&csb[rb + cx - r + 1]));
                    if (cx + r <= GC - 1)
                        scan_range(__ldg(&csb[rb + cx + r]), __ldg(&csb[rb + cx + r + 1]));
                }
            }
        }
    }
    if (!done) (void)merge11();   // full grid scanned; final exact merge

    // ---- epilogue: lane kk owns neighbor kk; lane 11 owns init features ----
    float acc[6];
    #pragma unroll
    for (int c = 0; c < 6; ++c) acc[c] = 0.f;

    if (lane < KP) {
        const int idx = myn;
        const float* vp = vel + ((size_t)b * NP + idx) * 3;
        float vx = vp[0], vy = vp[1], vz = vp[2];
        const int fv = 30 + lane * 3;
        #pragma unroll
        for (int c = 0; c < 6; ++c)
            acc[c] += Wsh[c * NFEAT + fv + 0] * vx
                    + Wsh[c * NFEAT + fv + 1] * vy
                    + Wsh[c * NFEAT + fv + 2] * vz;
        if (lane >= 1) {
            const float* pp = pos + ((size_t)b * NP + idx) * 3;
            float ox = pp[0] - q.x, oy = pp[1] - q.y, oz = pp[2] - q.z;
            const int fo = (lane - 1) * 3;
            #pragma unroll
            for (int c = 0; c < 6; ++c)
                acc[c] += Wsh[c * NFEAT + fo + 0] * ox
                        + Wsh[c * NFEAT + fo + 1] * oy
                        + Wsh[c * NFEAT + fo + 2] * oz;
        }
    } else if (lane == KP) {
        float i0 = init_cfg[b * 3 + 0];
        float i1 = init_cfg[b * 3 + 1];
        float i2 = init_cfg[b * 3 + 2];
        #pragma unroll
        for (int c = 0; c < 6; ++c)
            acc[c] += Wsh[c * NFEAT + 63] * i0
                    + Wsh[c * NFEAT + 64] * i1
                    + Wsh[c * NFEAT + 65] * i2;
    }
    #pragma unroll
    for (int o = 16; o > 0; o >>= 1) {
        #pragma unroll
        for (int c = 0; c < 6; ++c)
            acc[c] += __shfl_xor_sync(0xFFFFFFFFu, acc[c], o);
    }
    if (lane == 0) {
        acc[0] += bsh[0] + q.x;
        acc[1] += bsh[1] + q.y;
        acc[2] += bsh[2] + q.z;
        acc[3] += bsh[3];
        acc[4] += bsh[4];
        acc[5] += bsh[5];
        float* o = out + ((size_t)b * NP + n) * 6;
        #pragma unroll
        for (int c = 0; c < 6; ++c) o[c] = acc[c];
    }
}

extern "C" void kernel_launch(void* const* d_in, const int* in_sizes, int n_in,
                              void* d_out, int out_size) {
    const float* pos      = (const float*)d_in[0];
    const float* vel      = (const float*)d_in[1];
    const float* init_cfg = (const float*)d_in[2];
    const float* W1 = (const float*)d_in[3];
    const float* b1 = (const float*)d_in[4];
    const float* W2 = (const float*)d_in[5];
    const float* b2 = (const float*)d_in[6];
    const float* W3 = (const float*)d_in[7];
    const float* b3 = (const float*)d_in[8];
    float* out = (float*)d_out;

    zero_kernel<<<16, 1024>>>();
    fold_weights_kernel<<<1, 512>>>(W1, b1, W2, b2, W3, b3);
    hist_kernel<<<64, 256>>>(pos);
    scan_kernel<<<NB, 512>>>();
    scatter_kernel<<<64, 256>>>(pos);

    dim3 grid(NP / WPQ, NB);
    search_kernel<<<grid, WPQ * 32>>>(pos, vel, init_cfg, out);
}

// round 12
// speedup vs baseline: 2.6077x; 1.2916x over previous
#include <cuda_runtime.h>

#define NB    4
#define NP    4096
#define KP    11                 // K+1 including self
#define NFEAT 66
#define GC    16                 // grid cells per axis
#define NCELL (GC*GC*GC)         // 4096
#define XMIN  (-4.5f)
#define HCELL (9.0f/(float)GC)   // 0.5625
#define IHINV ((float)GC/9.0f)
#define WPQ   8                  // warps (queries) per search block

typedef unsigned long long ull;
#define SENT 0xFFFFFFFFFFFFFFFFull
#define FULLM 0xFFFFFFFFu

__device__ float  g_Weff[6 * NFEAT];
__device__ float  g_beff[6];
__device__ float4 g_spos[NB][NP];          // x,y,z, idx-as-float-bits
__device__ int    g_cs[NB][NCELL + 1];

__device__ __forceinline__ int cell1(float v) {
    int c = (int)(__fmul_rn(__fsub_rn(v, XMIN), IHINV));
    return min(GC - 1, max(0, c));
}
__device__ __forceinline__ unsigned f2ord(float f) {
    unsigned u = __float_as_uint(f);
    return u ^ (((int)u >> 31) | 0x80000000u);
}

// ---------------------------------------------------------------------------
// Fold 3 linear layers into one 6x66 affine map; weights staged via smem.
__global__ void __launch_bounds__(512)
fold_weights_kernel(const float* __restrict__ W1, const float* __restrict__ b1,
                    const float* __restrict__ W2, const float* __restrict__ b2,
                    const float* __restrict__ W3, const float* __restrict__ b3) {
    __shared__ float sW1[32 * NFEAT];
    __shared__ float sW2[16 * 32];
    __shared__ float sW3[6 * 16];
    __shared__ float sb1[32], sb2[16];
    __shared__ float W32[6 * 32];
    __shared__ float bh[16];
    int t = threadIdx.x;
    for (int i = t; i < 32 * NFEAT; i += 512) sW1[i] = W1[i];
    if (t < 512) sW2[t] = W2[t];
    if (t < 96) sW3[t] = W3[t];
    if (t < 32) sb1[t] = b1[t];
    if (t < 16) sb2[t] = b2[t];
    __syncthreads();
    if (t < 192) {                      // W32 = W3 @ W2
        int c = t >> 5, jj = t & 31;
        float s = 0.f;
        #pragma unroll
        for (int i = 0; i < 16; ++i) s += sW3[c * 16 + i] * sW2[i * 32 + jj];
        W32[c * 32 + jj] = s;
    } else if (t < 208) {               // bh = W2 @ b1 + b2
        int i = t - 192;
        float s = sb2[i];
        #pragma unroll
        for (int j = 0; j < 32; ++j) s += sW2[i * 32 + j] * sb1[j];
        bh[i] = s;
    }
    __syncthreads();
    if (t < 396) {                      // Weff = W32 @ W1
        int c = t / NFEAT, f = t % NFEAT;
        float s = 0.f;
        #pragma unroll
        for (int jj = 0; jj < 32; ++jj) s += W32[c * 32 + jj] * sW1[jj * NFEAT + f];
        g_Weff[c * NFEAT + f] = s;
    } else if (t < 402) {               // beff = W3 @ bh + b3
        int c = t - 396;
        float s = b3[c];
        #pragma unroll
        for (int i = 0; i < 16; ++i) s += sW3[c * 16 + i] * bh[i];
        g_beff[c] = s;
    }
}

// ---------------------------------------------------------------------------
// Fused grid build: one block per batch. smem hist -> shuffle scan -> scatter.
#define BT 512
__global__ void __launch_bounds__(BT)
build_grid_kernel(const float* __restrict__ pos) {
    __shared__ int hist[NCELL];       // counts, then scatter cursors
    __shared__ int cstart[NCELL];     // cell starts
    __shared__ int wsum[BT / 32];

    const int b = blockIdx.x;
    const int t = threadIdx.x;
    const int lane = t & 31, w = t >> 5;
    const float* pb = pos + (size_t)b * NP * 3;

    for (int i = t; i < NCELL; i += BT) hist[i] = 0;
    __syncthreads();

    int  myc[NP / BT];
    #pragma unroll
    for (int k = 0; k < NP / BT; ++k) {
        int i = t + k * BT;
        float x = pb[3 * i + 0], y = pb[3 * i + 1], z = pb[3 * i + 2];
        int c = (cell1(z) * GC + cell1(y)) * GC + cell1(x);
        myc[k] = c;
        atomicAdd(&hist[c], 1);
    }
    __syncthreads();

    // exclusive scan of NCELL counts: 8 cells/thread + warp-shuffle scan
    {
        int base = t * (NCELL / BT);
        int ex[NCELL / BT]; int s = 0;
        #pragma unroll
        for (int k = 0; k < NCELL / BT; ++k) { ex[k] = s; s += hist[base + k]; }
        int v = s;
        #pragma unroll
        for (int off = 1; off < 32; off <<= 1) {
            int u = __shfl_up_sync(FULLM, v, off);
            if (lane >= off) v += u;
        }
        if (lane == 31) wsum[w] = v;
        __syncthreads();
        if (w == 0) {
            int wv = (lane < BT / 32) ? wsum[lane] : 0;
            #pragma unroll
            for (int off = 1; off < 32; off <<= 1) {
                int u = __shfl_up_sync(FULLM, wv, off);
                if (lane >= off) wv += u;
            }
            if (lane < BT / 32) wsum[lane] = wv;
        }
        __syncthreads();
        int woff = (w == 0) ? 0 : wsum[w - 1];
        int tbase = woff + (v - s);          // exclusive prefix for this thread
        #pragma unroll
        for (int k = 0; k < NCELL / BT; ++k) {
            int st = tbase + ex[k];
            cstart[base + k] = st;
            g_cs[b][base + k] = st;
        }
        if (t == 0) g_cs[b][NCELL] = NP;
    }
    __syncthreads();
    // reuse hist as cursors
    for (int i = t; i < NCELL; i += BT) hist[i] = cstart[i];
    __syncthreads();

    #pragma unroll
    for (int k = 0; k < NP / BT; ++k) {
        int i = t + k * BT;
        float x = pb[3 * i + 0], y = pb[3 * i + 1], z = pb[3 * i + 2];
        int off = atomicAdd(&hist[myc[k]], 1);
        g_spos[b][off] = make_float4(x, y, z, __int_as_float(i));
    }
}

// ---------------------------------------------------------------------------
// Search: one warp per query. Per-lane sorted top-11 on u64 keys
// (ord(d2)<<32 | orig_idx). Ring-break test: REDUX.SUM count of keys below
// bound (capped per-lane count is exact -- see proof in commit msg).
// Final assignment: single 11-round min-extract on 2x REDUX.MIN per round.
// d2 arithmetic bit-pinned to the reference's XLA lowering.
__global__ void __launch_bounds__(WPQ * 32)
search_kernel(const float* __restrict__ pos,
              const float* __restrict__ vel,
              const float* __restrict__ init_cfg,
              float* __restrict__ out) {
    __shared__ float Wsh[6 * NFEAT];
    __shared__ float bsh[8];
    const int tid = threadIdx.x;
    for (int i = tid; i < 6 * NFEAT; i += WPQ * 32) Wsh[i] = g_Weff[i];
    if (tid < 6) bsh[tid] = g_beff[tid];
    __syncthreads();

    const int wid  = tid >> 5;
    const int lane = tid & 31;
    const int b    = blockIdx.y;
    const int s_q  = blockIdx.x * WPQ + wid;      // sorted query index

    const float4 q = g_spos[b][s_q];
    const int    n = __float_as_int(q.w);         // original query index
    const float qsq = __fadd_rn(__fadd_rn(__fmul_rn(q.x, q.x), __fmul_rn(q.y, q.y)),
                                __fmul_rn(q.z, q.z));
    const int cx = cell1(q.x), cy = cell1(q.y), cz = cell1(q.z);
    const int*    csb = g_cs[b];
    const float4* sp  = g_spos[b];

    ull hk[KP];
    #pragma unroll
    for (int s = 0; s < KP; ++s) hk[s] = SENT;

    auto scan_range = [&](int a, int e) {
        for (int i = a + lane; i < e; i += 32) {
            float4 p = __ldg(&sp[i]);
            float psq = __fadd_rn(__fadd_rn(__fmul_rn(p.x, p.x), __fmul_rn(p.y, p.y)),
                                  __fmul_rn(p.z, p.z));
            float dot = __fmul_rn(q.x, p.x);
            dot = __fmaf_rn(q.y, p.y, dot);
            dot = __fmaf_rn(q.z, p.z, dot);
            float S  = __fadd_rn(qsq, psq);
            float d2 = __fsub_rn(S, __fmul_rn(2.0f, dot));
            ull key = ((ull)f2ord(d2) << 32) | (unsigned)__float_as_int(p.w);
            if (key < hk[KP - 1]) {
                hk[KP - 1] = key;
                #pragma unroll
                for (int s = KP - 1; s > 0; --s) {
                    if (hk[s] < hk[s - 1]) { ull t2 = hk[s - 1]; hk[s - 1] = hk[s]; hk[s] = t2; }
                    else break;
                }
            }
        }
    };

    // rings 0..1: 3x3x3 neighborhood
    #pragma unroll
    for (int dz = -1; dz <= 1; ++dz) {
        int z = cz + dz; if ((unsigned)z >= GC) continue;
        #pragma unroll
        for (int dy = -1; dy <= 1; ++dy) {
            int y = cy + dy; if ((unsigned)y >= GC) continue;
            int rb = (z * GC + y) * GC;
            int xlo = max(cx - 1, 0), xhi = min(cx + 1, GC - 1);
            scan_range(__ldg(&csb[rb + xlo]), __ldg(&csb[rb + xhi + 1]));
        }
    }

    for (int r = 2; r <= GC - 1; ++r) {
        // Exact break test: >= 11 union keys strictly below the ring bound?
        // Unscanned cells (rings >= r) hold points >= (r-1)*H away.
        float bd = 0.999f * (float)(r - 1) * HCELL;
        unsigned bkey = f2ord(__fmul_rn(bd, bd));
        unsigned cnt = 0;
        #pragma unroll
        for (int s = 0; s < KP; ++s) cnt += ((unsigned)(hk[s] >> 32) < bkey) ? 1u : 0u;
        unsigned tot = __reduce_add_sync(FULLM, cnt);
        if (tot >= KP) break;

        int zlo = max(cz - r, 0), zhi = min(cz + r, GC - 1);
        for (int z = zlo; z <= zhi; ++z) {
            int adz = abs(z - cz);
            int ylo = max(cy - r, 0), yhi = min(cy + r, GC - 1);
            for (int y = ylo; y <= yhi; ++y) {
                bool face = (adz == r) || (abs(y - cy) == r);
                int rb = (z * GC + y) * GC;
                if (face) {
                    int xlo = max(cx - r, 0), xhi = min(cx + r, GC - 1);
                    scan_range(__ldg(&csb[rb + xlo]), __ldg(&csb[rb + xhi + 1]));
                } else {
                    if (cx - r >= 0)
                        scan_range(__ldg(&csb[rb + cx - r]), __ldg(&csb[rb + cx - r + 1]));
                    if (cx + r <= GC - 1)
                        scan_range(__ldg(&csb[rb + cx + r]), __ldg(&csb[rb + cx + r + 1]));
                }
            }
        }
    }

    // Final exact merge: 11 rounds of warp min-extraction (REDUX.MIN x2).
    // Lane s captures neighbor s's original index. Keys unique (idx embedded).
    int myn = 0;
    {
        ull ck[KP];
        #pragma unroll
        for (int s = 0; s < KP; ++s) ck[s] = hk[s];
        #pragma unroll
        for (int s = 0; s < KP; ++s) {
            unsigned hi  = (unsigned)(ck[0] >> 32);
            unsigned mhi = __reduce_min_sync(FULLM, hi);
            unsigned lo  = (hi == mhi) ? (unsigned)(ck[0] & 0xFFFFFFFFull) : 0xFFFFFFFFu;
            unsigned mlo = __reduce_min_sync(FULLM, lo);
            ull m = ((ull)mhi << 32) | mlo;
            if (lane == s) myn = (int)mlo;
            if (ck[0] == m) {                  // exactly one lane pops
                #pragma unroll
                for (int t2 = 0; t2 < KP - 1; ++t2) ck[t2] = ck[t2 + 1];
                ck[KP - 1] = SENT;
            }
        }
    }

    // ---- epilogue: lane kk owns neighbor kk; lane 11 owns init features ----
    float acc[6];
    #pragma unroll
    for (int c = 0; c < 6; ++c) acc[c] = 0.f;

    if (lane < KP) {
        const int idx = myn;
        const float* vp = vel + ((size_t)b * NP + idx) * 3;
        float vx = vp[0], vy = vp[1], vz = vp[2];
        const int fv = 30 + lane * 3;
        #pragma unroll
        for (int c = 0; c < 6; ++c)
            acc[c] += Wsh[c * NFEAT + fv + 0] * vx
                    + Wsh[c * NFEAT + fv + 1] * vy
                    + Wsh[c * NFEAT + fv + 2] * vz;
        if (lane >= 1) {
            const float* pp = pos + ((size_t)b * NP + idx) * 3;
            float ox = pp[0] - q.x, oy = pp[1] - q.y, oz = pp[2] - q.z;
            const int fo = (lane - 1) * 3;
            #pragma unroll
            for (int c = 0; c < 6; ++c)
                acc[c] += Wsh[c * NFEAT + fo + 0] * ox
                        + Wsh[c * NFEAT + fo + 1] * oy
                        + Wsh[c * NFEAT + fo + 2] * oz;
        }
    } else if (lane == KP) {
        float i0 = init_cfg[b * 3 + 0];
        float i1 = init_cfg[b * 3 + 1];
        float i2 = init_cfg[b * 3 + 2];
        #pragma unroll
        for (int c = 0; c < 6; ++c)
            acc[c] += Wsh[c * NFEAT + 63] * i0
                    + Wsh[c * NFEAT + 64] * i1
                    + Wsh[c * NFEAT + 65] * i2;
    }
    #pragma unroll
    for (int o = 16; o > 0; o >>= 1) {
        #pragma unroll
        for (int c = 0; c < 6; ++c)
            acc[c] += __shfl_xor_sync(FULLM, acc[c], o);
    }
    if (lane == 0) {
        acc[0] += bsh[0] + q.x;
        acc[1] += bsh[1] + q.y;
        acc[2] += bsh[2] + q.z;
        acc[3] += bsh[3];
        acc[4] += bsh[4];
        acc[5] += bsh[5];
        float* o = out + ((size_t)b * NP + n) * 6;
        #pragma unroll
        for (int c = 0; c < 6; ++c) o[c] = acc[c];
    }
}

extern "C" void kernel_launch(void* const* d_in, const int* in_sizes, int n_in,
                              void* d_out, int out_size) {
    const float* pos      = (const float*)d_in[0];
    const float* vel      = (const float*)d_in[1];
    const float* init_cfg = (const float*)d_in[2];
    const float* W1 = (const float*)d_in[3];
    const float* b1 = (const float*)d_in[4];
    const float* W2 = (const float*)d_in[5];
    const float* b2 = (const float*)d_in[6];
    const float* W3 = (const float*)d_in[7];
    const float* b3 = (const float*)d_in[8];
    float* out = (float*)d_out;

    fold_weights_kernel<<<1, 512>>>(W1, b1, W2, b2, W3, b3);
    build_grid_kernel<<<NB, BT>>>(pos);

    dim3 grid(NP / WPQ, NB);
    search_kernel<<<grid, WPQ * 32>>>(pos, vel, init_cfg, out);
}